// round 7
// baseline (speedup 1.0000x reference)
#include <cuda_runtime.h>
#include <math.h>

#define BATCH 2048
#define LSEQ  70
#define DIN   15
#define HID   16
#define NF    4
#define KW    40
#define CDIM  20          // DIN + 1 + NF
#define LP    31          // LSEQ - KW + 1
#define Z0    64
#define NOUT  128         // 2*Z0
#define SIGCH 8420        // C + C^2 + C^3

#define KSPLIT 18
#define KCHUNK 480        // 18*480 = 8640 >= 8420
#define KB     16
#define NIT    (KCHUNK / KB)   // 30
#define TM     128
#define TN     128

#define ASTRIDE 132       // row stride of As (floats), 16B-aligned rows
#define BSTRIDE 129       // row stride of Bs (float2), padded

typedef unsigned long long ull;

// Scratch (static device arrays: allocation-free per harness rules)
__device__ float g_sig[(size_t)BATCH * SIGCH];            // 69 MB
__device__ float g_zpart[(size_t)KSPLIT * BATCH * NOUT];  // 18.9 MB

// Packed dual-FMA (Blackwell f32x2): acc = a*b + acc
#define FFMA2(acc, a, b) \
    asm("fma.rn.f32x2 %0, %1, %2, %0;" : "+l"(acc) : "l"(a), "l"(b))
#define DUP2(dst, s) \
    asm("mov.b64 %0, {%1,%1};" : "=l"(dst) : "f"(s))

// ---------------------------------------------------------------------------
// Kernel 1: per-batch path (conv chain) + depth-3 signature
// One block per batch, 224 threads.
// conv1: o-paired FFMA2 (64 threads); scan: k-paired FFMA2, barrier-free.
// ---------------------------------------------------------------------------
__global__ __launch_bounds__(224, 4) void sig_kernel(
    const float* __restrict__ x,    // (B, L, DIN)
    const float* __restrict__ w1,   // (HID, DIN, KW)
    const float* __restrict__ b1,
    const float* __restrict__ w2,   // (HID, HID)
    const float* __restrict__ b2,
    const float* __restrict__ w3,   // (NF, HID)
    const float* __restrict__ b3)
{
    __shared__ __align__(16) float2 xs2[DIN * 72];       // (x,x) dup, c-major, pad l=70,71
    __shared__ __align__(16) float2 w1p[8 * DIN * KW];   // (w[o],w[o+8])
    __shared__ float paths[LP * CDIM];                   // 620
    __shared__ __align__(16) float u[992];               // h1s[0..496) | h2s[496..992); later dsm[0..620)

    const int b = blockIdx.x;
    const int t = threadIdx.x;

    float* h1s = u;
    float* h2s = u + 496;

    // ---- build xs2 (duplicated, c-major) and w1p (o-paired) ----
    for (int i = t; i < LSEQ * DIN; i += 224) {
        int l = i / DIN, c = i % DIN;
        float v = x[(size_t)b * LSEQ * DIN + i];
        xs2[c * 72 + l] = make_float2(v, v);
    }
    if (t < 2 * DIN) {                                   // zero pad rows 70,71
        int c = t % DIN, l = 70 + t / DIN;
        xs2[c * 72 + l] = make_float2(0.f, 0.f);
    }
    {
        float* w1pf = (float*)w1p;
        for (int i = t; i < HID * DIN * KW; i += 224) {
            int o = i / (DIN * KW), r = i % (DIN * KW);
            w1pf[(size_t)((o & 7) * (DIN * KW) + r) * 2 + (o >> 3)] = w1[i];
        }
    }
    __syncthreads();

    // ---- conv1: 64 threads, each (op, op+8) x 4 l's; 2 LDS.64 + 4 FFMA2 per k
    if (t < 64) {
        const int op = t >> 3;
        const int lg = t & 7;
        const int l0 = lg * 4;
        ull acc0 = 0ull, acc1 = 0ull, acc2 = 0ull, acc3 = 0ull;
        #pragma unroll 1
        for (int c = 0; c < DIN; ++c) {
            const float2* xr = &xs2[c * 72 + l0];
            const float2* wr = &w1p[(op * DIN + c) * KW];
            ull xd0 = *(const ull*)&xr[0];
            ull xd1 = *(const ull*)&xr[1];
            ull xd2 = *(const ull*)&xr[2];
            #pragma unroll
            for (int k = 0; k < KW; ++k) {
                ull xd3 = *(const ull*)&xr[k + 3];
                ull wv  = *(const ull*)&wr[k];
                FFMA2(acc0, xd0, wv);
                FFMA2(acc1, xd1, wv);
                FFMA2(acc2, xd2, wv);
                FFMA2(acc3, xd3, wv);
                xd0 = xd1; xd1 = xd2; xd2 = xd3;
            }
        }
        float blo = b1[op], bhi = b1[op + 8];
        ull accs[4] = {acc0, acc1, acc2, acc3};
        #pragma unroll
        for (int j = 0; j < 4; ++j) {
            int l = l0 + j;
            if (l < LP) {
                float2 v = *(float2*)&accs[j];
                h1s[op * LP + l]       = fmaxf(v.x + blo, 0.f);
                h1s[(op + 8) * LP + l] = fmaxf(v.y + bhi, 0.f);
            }
        }
    }
    __syncthreads();

    // ---- conv2 (1x1) + relu ----
    for (int idx = t; idx < HID * LP; idx += 224) {
        int o = idx / LP, l = idx % LP;
        float s = b2[o];
        #pragma unroll
        for (int c2 = 0; c2 < HID; ++c2)
            s = fmaf(w2[o * HID + c2], h1s[c2 * LP + l], s);
        h2s[idx] = fmaxf(s, 0.f);
    }
    __syncthreads();

    // ---- conv3 (1x1) + assemble path [orig(15) | time(1) | conv_out(4)] ----
    for (int idx = t; idx < LP * CDIM; idx += 224) {
        int l = idx / CDIM, c = idx % CDIM;
        float v;
        if (c < DIN) {
            v = xs2[c * 72 + (KW - 1 + l)].x;
        } else if (c == DIN) {
            v = (float)l * (1.0f / (LP - 1));
        } else {
            int f = c - DIN - 1;
            float s = b3[f];
            #pragma unroll
            for (int c2 = 0; c2 < HID; ++c2)
                s = fmaf(w3[f * HID + c2], h2s[c2 * LP + l], s);
            v = s;
        }
        paths[idx] = v;
    }
    __syncthreads();

    // ---- increments (h1s/h2s dead; dsm overlays u) ----
    float* dsm = u;
    for (int idx = t; idx < LP * CDIM; idx += 224) {
        int l = idx / CDIM;
        dsm[idx] = paths[idx] - (l ? paths[idx - CDIM] : 0.f);
    }
    __syncthreads();

    // ---- depth-3 signature (Chen), barrier-free, k-paired FFMA2 ----
    const int i0 = t / CDIM;
    const int j0 = t % CDIM;
    float s1a = 0.f, s1b = 0.f, s2a = 0.f, s2b = 0.f;
    ull s3a2[10], s3b2[10];
    #pragma unroll
    for (int q = 0; q < 10; ++q) { s3a2[q] = 0ull; s3b2[q] = 0ull; }

    if (t < 200) {
        #pragma unroll 2
        for (int s = 0; s < LP; ++s) {
            const float* dr = &dsm[s * CDIM];
            float dj  = dr[j0];
            float dia = dr[i0];
            float dib = dr[i0 + 10];
            float A0 = fmaf(dj, fmaf(dia, 1.f / 6.f, 0.5f * s1a), s2a);
            float A1 = fmaf(dj, fmaf(dib, 1.f / 6.f, 0.5f * s1b), s2b);
            s2a = fmaf(dj, fmaf(dia, 0.5f, s1a), s2a);
            s2b = fmaf(dj, fmaf(dib, 0.5f, s1b), s2b);
            s1a += dia;
            s1b += dib;
            ull A0p, A1p;
            DUP2(A0p, A0);
            DUP2(A1p, A1);
            const ulonglong2* dv = (const ulonglong2*)dr;   // 16B aligned (s*80B)
            #pragma unroll
            for (int q = 0; q < 5; ++q) {
                ulonglong2 p = dv[q];                        // d[4q..4q+3] as 2 pairs
                FFMA2(s3a2[2 * q],     A0p, p.x);
                FFMA2(s3a2[2 * q + 1], A0p, p.y);
                FFMA2(s3b2[2 * q],     A1p, p.x);
                FFMA2(s3b2[2 * q + 1], A1p, p.y);
            }
        }
    }

    // ---- write signature: [s1(20) | s2(400) | s3(8000)] ----
    size_t base = (size_t)b * SIGCH;
    if (t < CDIM) g_sig[base + t] = paths[(LP - 1) * CDIM + t];   // s1 telescopes
    if (t < 200) {
        g_sig[base + CDIM + t]       = s2a;
        g_sig[base + CDIM + 200 + t] = s2b;
        size_t s3base = base + CDIM + CDIM * CDIM;
        ulonglong2* oa = (ulonglong2*)&g_sig[s3base + (size_t)t * CDIM];
        ulonglong2* ob = (ulonglong2*)&g_sig[s3base + (size_t)(t + 200) * CDIM];
        #pragma unroll
        for (int q = 0; q < 5; ++q) {
            ulonglong2 va; va.x = s3a2[2 * q]; va.y = s3a2[2 * q + 1];
            ulonglong2 vb; vb.x = s3b2[2 * q]; vb.y = s3b2[2 * q + 1];
            oa[q] = va;
            ob[q] = vb;
        }
    }
}

// ---------------------------------------------------------------------------
// Kernel 2: split-K GEMM, packed f32x2 FMAs, double-buffered, KB=16
// ---------------------------------------------------------------------------
__global__ __launch_bounds__(256, 2) void gemm_kernel(const float* __restrict__ wout)
{
    extern __shared__ float sm[];
    float*  As0 = sm;
    float*  As1 = sm + KB * ASTRIDE;
    float2* Bs0 = (float2*)(sm + 2 * KB * ASTRIDE);
    float2* Bs1 = Bs0 + KB * BSTRIDE;

    const int m0    = blockIdx.x * TM;
    const int kbase = blockIdx.y * KCHUNK;
    const int t  = threadIdx.x;
    const int tx = t & 15;     // n lane: n = j*16 + tx
    const int ty = t >> 4;     // m group: m = ty*8 + 2*i (+1)

    ull acc[4][8];
    #pragma unroll
    for (int i = 0; i < 4; ++i)
        #pragma unroll
        for (int j = 0; j < 8; ++j) acc[i][j] = 0ull;

    float4 ra[2], rb[2];

    #define LOAD_TILE(k0)                                                     \
        {                                                                     \
            _Pragma("unroll")                                                 \
            for (int i = 0; i < 2; ++i) {                                     \
                int idx = t + i * 256;                                        \
                int r = idx >> 2, q = idx & 3;                                \
                int k = (k0) + q * 4;                                         \
                if (k < SIGCH) {                                              \
                    ra[i] = *(const float4*)&g_sig[(size_t)(m0 + r) * SIGCH + k]; \
                    rb[i] = *(const float4*)&wout[(size_t)r * SIGCH + k];     \
                } else {                                                      \
                    ra[i] = make_float4(0.f, 0.f, 0.f, 0.f);                  \
                    rb[i] = make_float4(0.f, 0.f, 0.f, 0.f);                  \
                }                                                             \
            }                                                                 \
        }

    #define STORE_TILE(Ad, Bd)                                                \
        {                                                                     \
            _Pragma("unroll")                                                 \
            for (int i = 0; i < 2; ++i) {                                     \
                int idx = t + i * 256;                                        \
                int r = idx >> 2, q = idx & 3;                                \
                (Ad)[(q * 4 + 0) * ASTRIDE + r] = ra[i].x;                    \
                (Ad)[(q * 4 + 1) * ASTRIDE + r] = ra[i].y;                    \
                (Ad)[(q * 4 + 2) * ASTRIDE + r] = ra[i].z;                    \
                (Ad)[(q * 4 + 3) * ASTRIDE + r] = ra[i].w;                    \
                (Bd)[(q * 4 + 0) * BSTRIDE + r] = make_float2(rb[i].x, rb[i].x); \
                (Bd)[(q * 4 + 1) * BSTRIDE + r] = make_float2(rb[i].y, rb[i].y); \
                (Bd)[(q * 4 + 2) * BSTRIDE + r] = make_float2(rb[i].z, rb[i].z); \
                (Bd)[(q * 4 + 3) * BSTRIDE + r] = make_float2(rb[i].w, rb[i].w); \
            }                                                                 \
        }

    LOAD_TILE(kbase);
    STORE_TILE(As0, Bs0);
    __syncthreads();

    for (int it = 0; it < NIT; ++it) {
        const float*  A = (it & 1) ? As1 : As0;
        const float2* B = (it & 1) ? Bs1 : Bs0;
        float*  An = (it & 1) ? As0 : As1;
        float2* Bn = (it & 1) ? Bs0 : Bs1;

        if (it + 1 < NIT) LOAD_TILE(kbase + (it + 1) * KB);

        #pragma unroll
        for (int kk = 0; kk < KB; ++kk) {
            ull a2[4], b2[8];
            #pragma unroll
            for (int i = 0; i < 2; ++i) {        // 2 broadcast LDS.128 (16B-aligned)
                ulonglong2 av = *(const ulonglong2*)&A[kk * ASTRIDE + ty * 8 + 4 * i];
                a2[2 * i]     = av.x;
                a2[2 * i + 1] = av.y;
            }
            #pragma unroll
            for (int j = 0; j < 8; ++j)
                b2[j] = *(const ull*)&B[kk * BSTRIDE + j * 16 + tx];
            #pragma unroll
            for (int i = 0; i < 4; ++i)
                #pragma unroll
                for (int j = 0; j < 8; ++j)
                    FFMA2(acc[i][j], a2[i], b2[j]);
        }

        if (it + 1 < NIT) STORE_TILE(An, Bn);
        __syncthreads();
    }

    float* zp = g_zpart + ((size_t)blockIdx.y * BATCH + m0) * NOUT;
    #pragma unroll
    for (int i = 0; i < 4; ++i)
        #pragma unroll
        for (int j = 0; j < 8; ++j) {
            float2 v = *(float2*)&acc[i][j];
            int m = ty * 8 + 2 * i;
            int n = j * 16 + tx;
            zp[(size_t)m * NOUT + n]       = v.x;
            zp[(size_t)(m + 1) * NOUT + n] = v.y;
        }
}

#define GEMM_SMEM (2 * KB * ASTRIDE * 4 + 2 * KB * BSTRIDE * 8)

// ---------------------------------------------------------------------------
// Kernel 3: reduce split-K partials + bias; mean | softplus(std)
// ---------------------------------------------------------------------------
__global__ __launch_bounds__(256) void epi_kernel(const float* __restrict__ bout,
                                                  float* __restrict__ out)
{
    int idx = blockIdx.x * 256 + threadIdx.x;
    if (idx >= BATCH * NOUT) return;
    int b = idx / NOUT, n = idx % NOUT;
    float s = bout[n];
    #pragma unroll
    for (int z = 0; z < KSPLIT; ++z)
        s += g_zpart[((size_t)z * BATCH + b) * NOUT + n];
    if (n < Z0) {
        out[(size_t)b * Z0 + n] = s;
    } else {
        float v = fmaxf(s, 0.f) + log1pf(expf(-fabsf(s)));   // stable softplus
        out[(size_t)BATCH * Z0 + (size_t)b * Z0 + (n - Z0)] = v;
    }
}

// ---------------------------------------------------------------------------
extern "C" void kernel_launch(void* const* d_in, const int* in_sizes, int n_in,
                              void* d_out, int out_size)
{
    const float* x    = (const float*)d_in[0];
    // d_in[1] = observed_tp (unused by the reference computation)
    const float* w1   = (const float*)d_in[2];
    const float* b1   = (const float*)d_in[3];
    const float* w2   = (const float*)d_in[4];
    const float* b2   = (const float*)d_in[5];
    const float* w3   = (const float*)d_in[6];
    const float* b3   = (const float*)d_in[7];
    const float* wout = (const float*)d_in[8];
    const float* bout = (const float*)d_in[9];
    float* out = (float*)d_out;

    cudaFuncSetAttribute(gemm_kernel,
                         cudaFuncAttributeMaxDynamicSharedMemorySize, GEMM_SMEM);

    sig_kernel<<<BATCH, 224>>>(x, w1, b1, w2, b2, w3, b3);
    gemm_kernel<<<dim3(BATCH / TM, KSPLIT), 256, GEMM_SMEM>>>(wout);
    epi_kernel<<<(BATCH * NOUT + 255) / 256, 256>>>(bout, out);
}

// round 10
// speedup vs baseline: 1.4367x; 1.4367x over previous
#include <cuda_runtime.h>
#include <cuda_bf16.h>
#include <math.h>
#include <stdint.h>

#define BATCH 2048
#define LSEQ  70
#define DIN   15
#define HID   16
#define NF    4
#define KW    40
#define CDIM  20          // DIN + 1 + NF
#define LP    31          // LSEQ - KW + 1
#define Z0    64
#define NOUT  128         // 2*Z0
#define SIGCH 8420        // C + C^2 + C^3

#define KTOT   8640       // padded K (zero tail), 9*960
#define KSPLIT 9
#define KCHUNK 960
#define KB     32         // k per pipeline stage (bf16 elems)
#define NKT    (KCHUNK / KB)        // 30
#define NITER  (3 * NKT)            // 90 virtual-K iterations (3 terms)

typedef unsigned long long ull;

// Scratch (static device arrays; zero-initialized at load — padded K tail
// [8420,8640) is never written and stays zero)
__device__ __nv_bfloat16 g_a0[(size_t)BATCH * KTOT];   // sig hi
__device__ __nv_bfloat16 g_a1[(size_t)BATCH * KTOT];   // sig lo
__device__ __nv_bfloat16 g_b0[(size_t)NOUT * KTOT];    // wout hi
__device__ __nv_bfloat16 g_b1[(size_t)NOUT * KTOT];    // wout lo
__device__ float g_zpart[(size_t)KSPLIT * BATCH * NOUT];

// ---------------------------------------------------------------------------
// helpers
// ---------------------------------------------------------------------------
__device__ __forceinline__ uint32_t smem_u32(const void* p) {
    uint32_t a;
    asm("{ .reg .u64 t; cvta.to.shared.u64 t, %1; cvt.u32.u64 %0, t; }"
        : "=r"(a) : "l"(p));
    return a;
}
__device__ __forceinline__ uint32_t lds_u32(uint32_t addr) {
    uint32_t v;
    asm volatile("ld.shared.b32 %0, [%1];" : "=r"(v) : "r"(addr));
    return v;
}
// 64B rows, 16B segs swizzled by seg ^ ((row>>1)&3): conflict-free for both
// cp.async 16B store phases and the mma fragment LDS.32 pattern.
__device__ __forceinline__ uint32_t swadr(uint32_t base, int row, int off) {
    return base + row * 64 + ((((off >> 4) ^ (row >> 1)) & 3) << 4) + (off & 15);
}
#define CPA16(dst, src) \
    asm volatile("cp.async.cg.shared.global [%0], [%1], 16;" :: "r"(dst), "l"(src))
#define CPA_COMMIT() asm volatile("cp.async.commit_group;" ::: "memory")
#define CPA_WAIT0()  asm volatile("cp.async.wait_group 0;" ::: "memory")
#define CPA_WAIT1()  asm volatile("cp.async.wait_group 1;" ::: "memory")

#define MMA16816(d, a, b) \
    asm volatile("mma.sync.aligned.m16n8k16.row.col.f32.bf16.bf16.f32 " \
        "{%0,%1,%2,%3}, {%4,%5,%6,%7}, {%8,%9}, {%0,%1,%2,%3};" \
        : "+f"((d)[0]), "+f"((d)[1]), "+f"((d)[2]), "+f"((d)[3]) \
        : "r"((a)[0]), "r"((a)[1]), "r"((a)[2]), "r"((a)[3]), \
          "r"((b)[0]), "r"((b)[1]))

// ---------------------------------------------------------------------------
// Kernel 1: per-batch path (conv chain) + depth-3 signature (R5 structure),
// emitting bf16 hi/lo split of the signature.
// ---------------------------------------------------------------------------
__global__ __launch_bounds__(224, 4) void sig_kernel(
    const float* __restrict__ x,    // (B, L, DIN)
    const float* __restrict__ w1,   // (HID, DIN, KW)
    const float* __restrict__ b1,
    const float* __restrict__ w2,   // (HID, HID)
    const float* __restrict__ b2,
    const float* __restrict__ w3,   // (NF, HID)
    const float* __restrict__ b3)
{
    __shared__ float xs[(LSEQ + 1) * DIN];               // 1065 (+pad row)
    __shared__ float h1s[HID * LP];                      // 496
    __shared__ float paths[LP * CDIM];                   // 620
    __shared__ float h2s[HID * LP];                      // 496
    __shared__ __align__(16) float dsm[LP * CDIM];       // 620
    __shared__ __align__(16) float w1s[HID * DIN * KW];  // 9600 = 38.4 KB

    const int b = blockIdx.x;
    const int t = threadIdx.x;

    for (int i = t; i < LSEQ * DIN; i += 224) xs[i] = x[(size_t)b * LSEQ * DIN + i];
    if (t < DIN) xs[LSEQ * DIN + t] = 0.f;
    {
        const float4* w4 = (const float4*)w1;
        float4* s4 = (float4*)w1s;
        for (int i = t; i < HID * DIN * KW / 4; i += 224) s4[i] = w4[i];
    }
    __syncthreads();

    // ---- conv1 (VALID, kernel 40): 128 threads, sliding window ----
    if (t < 128) {
        const int o  = t >> 3;
        const int l0 = (t & 7) * 4;
        float a0 = 0.f, a1 = 0.f, a2 = 0.f, a3 = 0.f;
        const float* wrow = &w1s[o * DIN * KW];
        #pragma unroll 1
        for (int c = 0; c < DIN; ++c) {
            float xw0 = xs[(l0 + 0) * DIN + c];
            float xw1 = xs[(l0 + 1) * DIN + c];
            float xw2 = xs[(l0 + 2) * DIN + c];
            const float4* wc4 = (const float4*)(wrow + c * KW);
            #pragma unroll
            for (int kq = 0; kq < KW / 4; ++kq) {
                float4 w4 = wc4[kq];
                float xw3;
                xw3 = xs[(l0 + 4*kq + 3) * DIN + c];
                a0 = fmaf(w4.x, xw0, a0); a1 = fmaf(w4.x, xw1, a1);
                a2 = fmaf(w4.x, xw2, a2); a3 = fmaf(w4.x, xw3, a3);
                xw0 = xw1; xw1 = xw2; xw2 = xw3;
                xw3 = xs[(l0 + 4*kq + 4) * DIN + c];
                a0 = fmaf(w4.y, xw0, a0); a1 = fmaf(w4.y, xw1, a1);
                a2 = fmaf(w4.y, xw2, a2); a3 = fmaf(w4.y, xw3, a3);
                xw0 = xw1; xw1 = xw2; xw2 = xw3;
                xw3 = xs[(l0 + 4*kq + 5) * DIN + c];
                a0 = fmaf(w4.z, xw0, a0); a1 = fmaf(w4.z, xw1, a1);
                a2 = fmaf(w4.z, xw2, a2); a3 = fmaf(w4.z, xw3, a3);
                xw0 = xw1; xw1 = xw2; xw2 = xw3;
                xw3 = xs[(l0 + 4*kq + 6) * DIN + c];
                a0 = fmaf(w4.w, xw0, a0); a1 = fmaf(w4.w, xw1, a1);
                a2 = fmaf(w4.w, xw2, a2); a3 = fmaf(w4.w, xw3, a3);
                xw0 = xw1; xw1 = xw2; xw2 = xw3;
            }
        }
        float bias = b1[o];
        if (l0 + 0 < LP) h1s[o * LP + l0 + 0] = fmaxf(a0 + bias, 0.f);
        if (l0 + 1 < LP) h1s[o * LP + l0 + 1] = fmaxf(a1 + bias, 0.f);
        if (l0 + 2 < LP) h1s[o * LP + l0 + 2] = fmaxf(a2 + bias, 0.f);
        if (l0 + 3 < LP) h1s[o * LP + l0 + 3] = fmaxf(a3 + bias, 0.f);
    }
    __syncthreads();

    // ---- conv2 (1x1) + relu ----
    for (int idx = t; idx < HID * LP; idx += 224) {
        int o = idx / LP, l = idx % LP;
        float s = b2[o];
        #pragma unroll
        for (int c2 = 0; c2 < HID; ++c2)
            s = fmaf(w2[o * HID + c2], h1s[c2 * LP + l], s);
        h2s[idx] = fmaxf(s, 0.f);
    }
    __syncthreads();

    // ---- conv3 (1x1) + assemble path ----
    for (int idx = t; idx < LP * CDIM; idx += 224) {
        int l = idx / CDIM, c = idx % CDIM;
        float v;
        if (c < DIN) {
            v = xs[(KW - 1 + l) * DIN + c];
        } else if (c == DIN) {
            v = (float)l * (1.0f / (LP - 1));
        } else {
            int f = c - DIN - 1;
            float s = b3[f];
            #pragma unroll
            for (int c2 = 0; c2 < HID; ++c2)
                s = fmaf(w3[f * HID + c2], h2s[c2 * LP + l], s);
            v = s;
        }
        paths[idx] = v;
    }
    __syncthreads();

    for (int idx = t; idx < LP * CDIM; idx += 224) {
        int l = idx / CDIM;
        dsm[idx] = paths[idx] - (l ? paths[idx - CDIM] : 0.f);
    }
    __syncthreads();

    // ---- depth-3 signature (Chen), barrier-free scan ----
    const int i0 = t / CDIM;
    const int j0 = t % CDIM;
    float s1a = 0.f, s1b = 0.f, s2a = 0.f, s2b = 0.f;
    float s3a[CDIM], s3b[CDIM];
    #pragma unroll
    for (int k = 0; k < CDIM; ++k) { s3a[k] = 0.f; s3b[k] = 0.f; }

    if (t < 200) {
        #pragma unroll 2
        for (int s = 0; s < LP; ++s) {
            const float* dr = &dsm[s * CDIM];
            float dj  = dr[j0];
            float dia = dr[i0];
            float dib = dr[i0 + 10];
            float A0 = fmaf(dj, fmaf(dia, 1.f / 6.f, 0.5f * s1a), s2a);
            float A1 = fmaf(dj, fmaf(dib, 1.f / 6.f, 0.5f * s1b), s2b);
            s2a = fmaf(dj, fmaf(dia, 0.5f, s1a), s2a);
            s2b = fmaf(dj, fmaf(dib, 0.5f, s1b), s2b);
            s1a += dia;
            s1b += dib;
            const float4* dv4 = (const float4*)dr;
            #pragma unroll
            for (int q = 0; q < 5; ++q) {
                float4 dv = dv4[q];
                s3a[q*4+0] = fmaf(A0, dv.x, s3a[q*4+0]);
                s3a[q*4+1] = fmaf(A0, dv.y, s3a[q*4+1]);
                s3a[q*4+2] = fmaf(A0, dv.z, s3a[q*4+2]);
                s3a[q*4+3] = fmaf(A0, dv.w, s3a[q*4+3]);
                s3b[q*4+0] = fmaf(A1, dv.x, s3b[q*4+0]);
                s3b[q*4+1] = fmaf(A1, dv.y, s3b[q*4+1]);
                s3b[q*4+2] = fmaf(A1, dv.z, s3b[q*4+2]);
                s3b[q*4+3] = fmaf(A1, dv.w, s3b[q*4+3]);
            }
        }
    }

    // ---- write signature as bf16 hi/lo: [s1(20) | s2(400) | s3(8000)] ----
    size_t base = (size_t)b * KTOT;
    if (t < CDIM) {
        float v = paths[(LP - 1) * CDIM + t];      // s1 telescopes
        __nv_bfloat16 h = __float2bfloat16_rn(v);
        g_a0[base + t] = h;
        g_a1[base + t] = __float2bfloat16_rn(v - __bfloat162float(h));
    }
    if (t < 200) {
        {
            __nv_bfloat16 h = __float2bfloat16_rn(s2a);
            g_a0[base + CDIM + t] = h;
            g_a1[base + CDIM + t] = __float2bfloat16_rn(s2a - __bfloat162float(h));
            h = __float2bfloat16_rn(s2b);
            g_a0[base + CDIM + 200 + t] = h;
            g_a1[base + CDIM + 200 + t] = __float2bfloat16_rn(s2b - __bfloat162float(h));
        }
        size_t r0 = base + 420 + (size_t)t * CDIM;
        size_t r1 = base + 420 + (size_t)(t + 200) * CDIM;
        #pragma unroll
        for (int q = 0; q < 5; ++q) {
            ull h0 = 0, l0p = 0, h1 = 0, l1p = 0;
            #pragma unroll
            for (int j = 0; j < 4; ++j) {
                float va = s3a[q*4+j];
                __nv_bfloat16 h = __float2bfloat16_rn(va);
                __nv_bfloat16 l = __float2bfloat16_rn(va - __bfloat162float(h));
                h0  |= (ull)__bfloat16_as_ushort(h) << (16 * j);
                l0p |= (ull)__bfloat16_as_ushort(l) << (16 * j);
                float vb = s3b[q*4+j];
                h = __float2bfloat16_rn(vb);
                l = __float2bfloat16_rn(vb - __bfloat162float(h));
                h1  |= (ull)__bfloat16_as_ushort(h) << (16 * j);
                l1p |= (ull)__bfloat16_as_ushort(l) << (16 * j);
            }
            *(ull*)&g_a0[r0 + q * 4] = h0;
            *(ull*)&g_a1[r0 + q * 4] = l0p;
            *(ull*)&g_a0[r1 + q * 4] = h1;
            *(ull*)&g_a1[r1 + q * 4] = l1p;
        }
    }
}

// ---------------------------------------------------------------------------
// Kernel 1b: wout -> bf16 hi/lo split (padded to KTOT)
// ---------------------------------------------------------------------------
__global__ __launch_bounds__(256) void wconv_kernel(const float* __restrict__ wout)
{
    int i = blockIdx.x * 256 + threadIdx.x;
    if (i >= NOUT * SIGCH) return;
    int n = i / SIGCH, k = i % SIGCH;
    float v = wout[i];
    __nv_bfloat16 h = __float2bfloat16_rn(v);
    g_b0[(size_t)n * KTOT + k] = h;
    g_b1[(size_t)n * KTOT + k] = __float2bfloat16_rn(v - __bfloat162float(h));
}

// ---------------------------------------------------------------------------
// Kernel 2: mma.sync bf16 3-term GEMM (emulated fp32)
// grid (16, 9): 128x128 block tile, 8 warps (warp tile 32x64).
// Virtual-K loop: 3 terms x 30 k-tiles of 32, cp.async double-buffered.
// ---------------------------------------------------------------------------
__global__ __launch_bounds__(256) void mma_gemm()
{
    __shared__ __align__(128) char smA[2][128 * 64];    // 8KB per buf
    __shared__ __align__(128) char smB[2][128 * 64];

    const int t   = threadIdx.x;
    const int wid = t >> 5;
    const int lid = t & 31;
    const int lr  = lid >> 2;        // fragment row group (0..7)
    const int lc  = lid & 3;         // fragment col group (0..3)
    const int mw  = (wid & 3) * 32;  // warp m offset in tile
    const int nw  = (wid >> 2) * 64; // warp n offset
    const int m0  = blockIdx.x * 128;
    const int kz  = blockIdx.y;
    const int kbase = kz * KCHUNK;

    const __nv_bfloat16* const Asrc[3] = { g_a0, g_a0, g_a1 };
    const __nv_bfloat16* const Bsrc[3] = { g_b0, g_b1, g_b0 };

    const uint32_t sA = smem_u32(smA);
    const uint32_t sB = smem_u32(smB);

    float acc[2][8][4];
    #pragma unroll
    for (int i = 0; i < 2; ++i)
        #pragma unroll
        for (int j = 0; j < 8; ++j)
            #pragma unroll
            for (int c = 0; c < 4; ++c) acc[i][j][c] = 0.f;

    // fill: 512 cp16 for A (128 rows x 4 segs) + 512 for B; 4 per thread
    #define FILL(bsel, itn)                                                    \
        {                                                                      \
            int term = (itn) / NKT;                                            \
            int k0 = kbase + ((itn) % NKT) * KB;                               \
            const __nv_bfloat16* Ap = Asrc[term];                              \
            const __nv_bfloat16* Bp = Bsrc[term];                              \
            _Pragma("unroll")                                                  \
            for (int i = 0; i < 2; ++i) {                                      \
                int id = t + i * 256;                                          \
                int row = id >> 2, seg = id & 3;                               \
                uint32_t da = sA + (uint32_t)(bsel) * 8192 + row * 64          \
                              + ((seg ^ ((row >> 1) & 3)) << 4);               \
                uint32_t db = sB + (uint32_t)(bsel) * 8192 + row * 64          \
                              + ((seg ^ ((row >> 1) & 3)) << 4);               \
                CPA16(da, (const char*)(Ap + (size_t)(m0 + row) * KTOT + k0 + seg * 8)); \
                CPA16(db, (const char*)(Bp + (size_t)row * KTOT + k0 + seg * 8));        \
            }                                                                  \
            CPA_COMMIT();                                                      \
        }

    FILL(0, 0);

    for (int it = 0; it < NITER; ++it) {
        if (it + 1 < NITER) FILL((it + 1) & 1, it + 1);
        if (it + 1 < NITER) CPA_WAIT1(); else CPA_WAIT0();
        __syncthreads();

        const uint32_t ab = sA + (uint32_t)(it & 1) * 8192;
        const uint32_t bb = sB + (uint32_t)(it & 1) * 8192;

        #pragma unroll
        for (int ks = 0; ks < 2; ++ks) {
            const int off = lc * 4 + ks * 32;
            uint32_t a[2][4];
            #pragma unroll
            for (int mi = 0; mi < 2; ++mi) {
                int r0 = mw + mi * 16 + lr;
                a[mi][0] = lds_u32(swadr(ab, r0,     off));
                a[mi][1] = lds_u32(swadr(ab, r0 + 8, off));
                a[mi][2] = lds_u32(swadr(ab, r0,     off + 16));
                a[mi][3] = lds_u32(swadr(ab, r0 + 8, off + 16));
            }
            uint32_t bfr[8][2];
            #pragma unroll
            for (int nj = 0; nj < 8; ++nj) {
                int rn = nw + nj * 8 + lr;
                bfr[nj][0] = lds_u32(swadr(bb, rn, off));
                bfr[nj][1] = lds_u32(swadr(bb, rn, off + 16));
            }
            #pragma unroll
            for (int mi = 0; mi < 2; ++mi)
                #pragma unroll
                for (int nj = 0; nj < 8; ++nj)
                    MMA16816(acc[mi][nj], a[mi], bfr[nj]);
        }
        __syncthreads();
    }

    // epilogue: write partials
    float* zp = g_zpart + ((size_t)kz * BATCH + m0) * NOUT;
    #pragma unroll
    for (int mi = 0; mi < 2; ++mi)
        #pragma unroll
        for (int nj = 0; nj < 8; ++nj) {
            int m = mw + mi * 16 + lr;
            int n = nw + nj * 8 + lc * 2;
            *(float2*)&zp[(size_t)m * NOUT + n] =
                make_float2(acc[mi][nj][0], acc[mi][nj][1]);
            *(float2*)&zp[(size_t)(m + 8) * NOUT + n] =
                make_float2(acc[mi][nj][2], acc[mi][nj][3]);
        }
}

// ---------------------------------------------------------------------------
// Kernel 3: reduce split-K partials + bias; mean | softplus(std)
// ---------------------------------------------------------------------------
__global__ __launch_bounds__(256) void epi_kernel(const float* __restrict__ bout,
                                                  float* __restrict__ out)
{
    int idx = blockIdx.x * 256 + threadIdx.x;
    if (idx >= BATCH * NOUT) return;
    int b = idx / NOUT, n = idx % NOUT;
    float s = bout[n];
    #pragma unroll
    for (int z = 0; z < KSPLIT; ++z)
        s += g_zpart[((size_t)z * BATCH + b) * NOUT + n];
    if (n < Z0) {
        out[(size_t)b * Z0 + n] = s;
    } else {
        float v = fmaxf(s, 0.f) + log1pf(expf(-fabsf(s)));   // stable softplus
        out[(size_t)BATCH * Z0 + (size_t)b * Z0 + (n - Z0)] = v;
    }
}

// ---------------------------------------------------------------------------
extern "C" void kernel_launch(void* const* d_in, const int* in_sizes, int n_in,
                              void* d_out, int out_size)
{
    const float* x    = (const float*)d_in[0];
    // d_in[1] = observed_tp (unused by the reference computation)
    const float* w1   = (const float*)d_in[2];
    const float* b1   = (const float*)d_in[3];
    const float* w2   = (const float*)d_in[4];
    const float* b2   = (const float*)d_in[5];
    const float* w3   = (const float*)d_in[6];
    const float* b3   = (const float*)d_in[7];
    const float* wout = (const float*)d_in[8];
    const float* bout = (const float*)d_in[9];
    float* out = (float*)d_out;

    wconv_kernel<<<(NOUT * SIGCH + 255) / 256, 256>>>(wout);
    sig_kernel<<<BATCH, 224>>>(x, w1, b1, w2, b2, w3, b3);
    mma_gemm<<<dim3(BATCH / 128, KSPLIT), 256>>>();
    epi_kernel<<<(BATCH * NOUT + 255) / 256, 256>>>(bout, out);
}

// round 11
// speedup vs baseline: 1.5815x; 1.1008x over previous
#include <cuda_runtime.h>
#include <cuda_bf16.h>
#include <math.h>
#include <stdint.h>

#define BATCH 2048
#define LSEQ  70
#define DIN   15
#define HID   16
#define NF    4
#define KW    40
#define CDIM  20          // DIN + 1 + NF
#define LP    31          // LSEQ - KW + 1
#define Z0    64
#define NOUT  128         // 2*Z0
#define SIGCH 8420        // C + C^2 + C^3

#define KTOT   8640       // padded K (zero tail), 9*960
#define KSPLIT 9
#define KCHUNK 960
#define KB     32         // k per pipeline stage (bf16 elems)
#define NKT    (KCHUNK / KB)        // 30 iterations (single pass, all 3 terms)

typedef unsigned long long ull;

// Scratch (static device arrays; zero-initialized at load — padded K tail
// [8420,8640) is never written and stays zero)
__device__ __nv_bfloat16 g_a0[(size_t)BATCH * KTOT];   // sig hi
__device__ __nv_bfloat16 g_a1[(size_t)BATCH * KTOT];   // sig lo
__device__ __nv_bfloat16 g_b0[(size_t)NOUT * KTOT];    // wout hi
__device__ __nv_bfloat16 g_b1[(size_t)NOUT * KTOT];    // wout lo
__device__ float g_zpart[(size_t)KSPLIT * BATCH * NOUT];

// ---------------------------------------------------------------------------
// helpers
// ---------------------------------------------------------------------------
__device__ __forceinline__ uint32_t smem_u32(const void* p) {
    uint32_t a;
    asm("{ .reg .u64 t; cvta.to.shared.u64 t, %1; cvt.u32.u64 %0, t; }"
        : "=r"(a) : "l"(p));
    return a;
}
// 64B rows, 16B segs swizzled by seg ^ ((row>>1)&3)
__device__ __forceinline__ uint32_t swadr(uint32_t base, int row, int off) {
    return base + row * 64 + ((((off >> 4) ^ (row >> 1)) & 3) << 4) + (off & 15);
}
#define CPA16(dst, src) \
    asm volatile("cp.async.cg.shared.global [%0], [%1], 16;" :: "r"(dst), "l"(src))
#define CPA_COMMIT() asm volatile("cp.async.commit_group;" ::: "memory")
#define CPA_WAIT0()  asm volatile("cp.async.wait_group 0;" ::: "memory")
#define CPA_WAIT1()  asm volatile("cp.async.wait_group 1;" ::: "memory")

#define MMA16816(d, a, b) \
    asm volatile("mma.sync.aligned.m16n8k16.row.col.f32.bf16.bf16.f32 " \
        "{%0,%1,%2,%3}, {%4,%5,%6,%7}, {%8,%9}, {%0,%1,%2,%3};" \
        : "+f"((d)[0]), "+f"((d)[1]), "+f"((d)[2]), "+f"((d)[3]) \
        : "r"((a)[0]), "r"((a)[1]), "r"((a)[2]), "r"((a)[3]), \
          "r"((b)[0]), "r"((b)[1]))

#define LDSM4(r, addr) \
    asm volatile("ldmatrix.sync.aligned.m8n8.x4.shared.b16 {%0,%1,%2,%3}, [%4];" \
        : "=r"((r)[0]), "=r"((r)[1]), "=r"((r)[2]), "=r"((r)[3]) : "r"(addr))

// ---------------------------------------------------------------------------
// Kernel 1: per-batch path (conv chain) + depth-3 signature,
// emitting bf16 hi/lo split of the signature. (proven R10 version)
// ---------------------------------------------------------------------------
__global__ __launch_bounds__(224, 4) void sig_kernel(
    const float* __restrict__ x,    // (B, L, DIN)
    const float* __restrict__ w1,   // (HID, DIN, KW)
    const float* __restrict__ b1,
    const float* __restrict__ w2,   // (HID, HID)
    const float* __restrict__ b2,
    const float* __restrict__ w3,   // (NF, HID)
    const float* __restrict__ b3)
{
    __shared__ float xs[(LSEQ + 1) * DIN];
    __shared__ float h1s[HID * LP];
    __shared__ float paths[LP * CDIM];
    __shared__ float h2s[HID * LP];
    __shared__ __align__(16) float dsm[LP * CDIM];
    __shared__ __align__(16) float w1s[HID * DIN * KW];  // 38.4 KB

    const int b = blockIdx.x;
    const int t = threadIdx.x;

    for (int i = t; i < LSEQ * DIN; i += 224) xs[i] = x[(size_t)b * LSEQ * DIN + i];
    if (t < DIN) xs[LSEQ * DIN + t] = 0.f;
    {
        const float4* w4 = (const float4*)w1;
        float4* s4 = (float4*)w1s;
        for (int i = t; i < HID * DIN * KW / 4; i += 224) s4[i] = w4[i];
    }
    __syncthreads();

    // ---- conv1 (VALID, kernel 40): 128 threads, sliding window ----
    if (t < 128) {
        const int o  = t >> 3;
        const int l0 = (t & 7) * 4;
        float a0 = 0.f, a1 = 0.f, a2 = 0.f, a3 = 0.f;
        const float* wrow = &w1s[o * DIN * KW];
        #pragma unroll 1
        for (int c = 0; c < DIN; ++c) {
            float xw0 = xs[(l0 + 0) * DIN + c];
            float xw1 = xs[(l0 + 1) * DIN + c];
            float xw2 = xs[(l0 + 2) * DIN + c];
            const float4* wc4 = (const float4*)(wrow + c * KW);
            #pragma unroll
            for (int kq = 0; kq < KW / 4; ++kq) {
                float4 w4 = wc4[kq];
                float xw3;
                xw3 = xs[(l0 + 4*kq + 3) * DIN + c];
                a0 = fmaf(w4.x, xw0, a0); a1 = fmaf(w4.x, xw1, a1);
                a2 = fmaf(w4.x, xw2, a2); a3 = fmaf(w4.x, xw3, a3);
                xw0 = xw1; xw1 = xw2; xw2 = xw3;
                xw3 = xs[(l0 + 4*kq + 4) * DIN + c];
                a0 = fmaf(w4.y, xw0, a0); a1 = fmaf(w4.y, xw1, a1);
                a2 = fmaf(w4.y, xw2, a2); a3 = fmaf(w4.y, xw3, a3);
                xw0 = xw1; xw1 = xw2; xw2 = xw3;
                xw3 = xs[(l0 + 4*kq + 5) * DIN + c];
                a0 = fmaf(w4.z, xw0, a0); a1 = fmaf(w4.z, xw1, a1);
                a2 = fmaf(w4.z, xw2, a2); a3 = fmaf(w4.z, xw3, a3);
                xw0 = xw1; xw1 = xw2; xw2 = xw3;
                xw3 = xs[(l0 + 4*kq + 6) * DIN + c];
                a0 = fmaf(w4.w, xw0, a0); a1 = fmaf(w4.w, xw1, a1);
                a2 = fmaf(w4.w, xw2, a2); a3 = fmaf(w4.w, xw3, a3);
                xw0 = xw1; xw1 = xw2; xw2 = xw3;
            }
        }
        float bias = b1[o];
        if (l0 + 0 < LP) h1s[o * LP + l0 + 0] = fmaxf(a0 + bias, 0.f);
        if (l0 + 1 < LP) h1s[o * LP + l0 + 1] = fmaxf(a1 + bias, 0.f);
        if (l0 + 2 < LP) h1s[o * LP + l0 + 2] = fmaxf(a2 + bias, 0.f);
        if (l0 + 3 < LP) h1s[o * LP + l0 + 3] = fmaxf(a3 + bias, 0.f);
    }
    __syncthreads();

    // ---- conv2 (1x1) + relu ----
    for (int idx = t; idx < HID * LP; idx += 224) {
        int o = idx / LP, l = idx % LP;
        float s = b2[o];
        #pragma unroll
        for (int c2 = 0; c2 < HID; ++c2)
            s = fmaf(w2[o * HID + c2], h1s[c2 * LP + l], s);
        h2s[idx] = fmaxf(s, 0.f);
    }
    __syncthreads();

    // ---- conv3 (1x1) + assemble path ----
    for (int idx = t; idx < LP * CDIM; idx += 224) {
        int l = idx / CDIM, c = idx % CDIM;
        float v;
        if (c < DIN) {
            v = xs[(KW - 1 + l) * DIN + c];
        } else if (c == DIN) {
            v = (float)l * (1.0f / (LP - 1));
        } else {
            int f = c - DIN - 1;
            float s = b3[f];
            #pragma unroll
            for (int c2 = 0; c2 < HID; ++c2)
                s = fmaf(w3[f * HID + c2], h2s[c2 * LP + l], s);
            v = s;
        }
        paths[idx] = v;
    }
    __syncthreads();

    for (int idx = t; idx < LP * CDIM; idx += 224) {
        int l = idx / CDIM;
        dsm[idx] = paths[idx] - (l ? paths[idx - CDIM] : 0.f);
    }
    __syncthreads();

    // ---- depth-3 signature (Chen), barrier-free scan ----
    const int i0 = t / CDIM;
    const int j0 = t % CDIM;
    float s1a = 0.f, s1b = 0.f, s2a = 0.f, s2b = 0.f;
    float s3a[CDIM], s3b[CDIM];
    #pragma unroll
    for (int k = 0; k < CDIM; ++k) { s3a[k] = 0.f; s3b[k] = 0.f; }

    if (t < 200) {
        #pragma unroll 2
        for (int s = 0; s < LP; ++s) {
            const float* dr = &dsm[s * CDIM];
            float dj  = dr[j0];
            float dia = dr[i0];
            float dib = dr[i0 + 10];
            float A0 = fmaf(dj, fmaf(dia, 1.f / 6.f, 0.5f * s1a), s2a);
            float A1 = fmaf(dj, fmaf(dib, 1.f / 6.f, 0.5f * s1b), s2b);
            s2a = fmaf(dj, fmaf(dia, 0.5f, s1a), s2a);
            s2b = fmaf(dj, fmaf(dib, 0.5f, s1b), s2b);
            s1a += dia;
            s1b += dib;
            const float4* dv4 = (const float4*)dr;
            #pragma unroll
            for (int q = 0; q < 5; ++q) {
                float4 dv = dv4[q];
                s3a[q*4+0] = fmaf(A0, dv.x, s3a[q*4+0]);
                s3a[q*4+1] = fmaf(A0, dv.y, s3a[q*4+1]);
                s3a[q*4+2] = fmaf(A0, dv.z, s3a[q*4+2]);
                s3a[q*4+3] = fmaf(A0, dv.w, s3a[q*4+3]);
                s3b[q*4+0] = fmaf(A1, dv.x, s3b[q*4+0]);
                s3b[q*4+1] = fmaf(A1, dv.y, s3b[q*4+1]);
                s3b[q*4+2] = fmaf(A1, dv.z, s3b[q*4+2]);
                s3b[q*4+3] = fmaf(A1, dv.w, s3b[q*4+3]);
            }
        }
    }

    // ---- write signature as bf16 hi/lo: [s1(20) | s2(400) | s3(8000)] ----
    size_t base = (size_t)b * KTOT;
    if (t < CDIM) {
        float v = paths[(LP - 1) * CDIM + t];      // s1 telescopes
        __nv_bfloat16 h = __float2bfloat16_rn(v);
        g_a0[base + t] = h;
        g_a1[base + t] = __float2bfloat16_rn(v - __bfloat162float(h));
    }
    if (t < 200) {
        {
            __nv_bfloat16 h = __float2bfloat16_rn(s2a);
            g_a0[base + CDIM + t] = h;
            g_a1[base + CDIM + t] = __float2bfloat16_rn(s2a - __bfloat162float(h));
            h = __float2bfloat16_rn(s2b);
            g_a0[base + CDIM + 200 + t] = h;
            g_a1[base + CDIM + 200 + t] = __float2bfloat16_rn(s2b - __bfloat162float(h));
        }
        size_t r0 = base + 420 + (size_t)t * CDIM;
        size_t r1 = base + 420 + (size_t)(t + 200) * CDIM;
        #pragma unroll
        for (int q = 0; q < 5; ++q) {
            ull h0 = 0, l0p = 0, h1 = 0, l1p = 0;
            #pragma unroll
            for (int j = 0; j < 4; ++j) {
                float va = s3a[q*4+j];
                __nv_bfloat16 h = __float2bfloat16_rn(va);
                __nv_bfloat16 l = __float2bfloat16_rn(va - __bfloat162float(h));
                h0  |= (ull)__bfloat16_as_ushort(h) << (16 * j);
                l0p |= (ull)__bfloat16_as_ushort(l) << (16 * j);
                float vb = s3b[q*4+j];
                h = __float2bfloat16_rn(vb);
                l = __float2bfloat16_rn(vb - __bfloat162float(h));
                h1  |= (ull)__bfloat16_as_ushort(h) << (16 * j);
                l1p |= (ull)__bfloat16_as_ushort(l) << (16 * j);
            }
            *(ull*)&g_a0[r0 + q * 4] = h0;
            *(ull*)&g_a1[r0 + q * 4] = l0p;
            *(ull*)&g_a0[r1 + q * 4] = h1;
            *(ull*)&g_a1[r1 + q * 4] = l1p;
        }
    }
}

// ---------------------------------------------------------------------------
// Kernel 1b: wout -> bf16 hi/lo split (padded to KTOT)
// ---------------------------------------------------------------------------
__global__ __launch_bounds__(256) void wconv_kernel(const float* __restrict__ wout)
{
    int i = blockIdx.x * 256 + threadIdx.x;
    if (i >= NOUT * SIGCH) return;
    int n = i / SIGCH, k = i % SIGCH;
    float v = wout[i];
    __nv_bfloat16 h = __float2bfloat16_rn(v);
    g_b0[(size_t)n * KTOT + k] = h;
    g_b1[(size_t)n * KTOT + k] = __float2bfloat16_rn(v - __bfloat162float(h));
}

// ---------------------------------------------------------------------------
// Kernel 2: mma.sync bf16 3-term GEMM, single pass over K.
// grid (16, 9): 128x128 block tile, 8 warps (warp tile 32x64).
// Per k-tile (32): load a0,a1,b0,b1 sub-tiles (32KB), ldmatrix fragments,
// 3 term-MMAs per fragment set (a0b0 + a0b1 + a1b0), double-buffered.
// ---------------------------------------------------------------------------
#define STAGE_SZ 32768
#define GEMM_SMEM (2 * STAGE_SZ)

__global__ __launch_bounds__(256) void mma_gemm()
{
    extern __shared__ __align__(128) char smem[];
    const uint32_t sb = smem_u32(smem);

    const int t    = threadIdx.x;
    const int wid  = t >> 5;
    const int lane = t & 31;
    const int lr   = lane >> 2;       // 0..7
    const int lc   = lane & 3;        // 0..3
    const int mw   = (wid & 3) * 32;  // warp m offset
    const int nw   = (wid >> 2) * 64; // warp n offset
    const int m0   = blockIdx.x * 128;
    const int kz   = blockIdx.y;
    const int kbase = kz * KCHUNK;

    float acc[2][8][4];
    #pragma unroll
    for (int i = 0; i < 2; ++i)
        #pragma unroll
        for (int j = 0; j < 8; ++j)
            #pragma unroll
            for (int c = 0; c < 4; ++c) acc[i][j][c] = 0.f;

    // per-thread cp.async mapping: 8 x 16B; sub-tiles A0|A1|B0|B1 @ 8KB each
    #define FILL(bsel, kt)                                                     \
        {                                                                      \
            int k0 = kbase + (kt) * KB;                                        \
            uint32_t stg = sb + (uint32_t)(bsel) * STAGE_SZ;                   \
            _Pragma("unroll")                                                  \
            for (int i = 0; i < 8; ++i) {                                      \
                int id = t + i * 256;                                          \
                int sub = id >> 9, w = id & 511;                               \
                int row = w >> 2, seg = w & 3;                                 \
                uint32_t dst = stg + sub * 8192 + row * 64                     \
                               + ((seg ^ ((row >> 1) & 3)) << 4);              \
                const __nv_bfloat16* src;                                      \
                if (sub == 0)      src = g_a0 + (size_t)(m0 + row) * KTOT;     \
                else if (sub == 1) src = g_a1 + (size_t)(m0 + row) * KTOT;     \
                else if (sub == 2) src = g_b0 + (size_t)row * KTOT;            \
                else               src = g_b1 + (size_t)row * KTOT;            \
                CPA16(dst, (const char*)(src + k0 + seg * 8));                 \
            }                                                                  \
            CPA_COMMIT();                                                      \
        }

    // ldmatrix lane-address components
    const int a_row = ((lane >> 3) & 1) * 8 + (lane & 7);  // row within 16-block
    const int a_col = ((lane >> 4) & 1) * 16;              // 0 or 16 bytes
    const int b_row = ((lane >> 4) & 1) * 8 + (lane & 7);
    const int b_col = ((lane >> 3) & 1) * 16;

    FILL(0, 0);

    for (int it = 0; it < NKT; ++it) {
        if (it + 1 < NKT) FILL((it + 1) & 1, it + 1);
        if (it + 1 < NKT) CPA_WAIT1(); else CPA_WAIT0();
        __syncthreads();

        uint32_t stg = sb + (uint32_t)(it & 1) * STAGE_SZ;
        uint32_t A0b = stg, A1b = stg + 8192, B0b = stg + 16384, B1b = stg + 24576;

        #pragma unroll
        for (int ks = 0; ks < 2; ++ks) {
            const int kc = ks * 32;   // byte offset of this k16 half
            uint32_t a0f[2][4], a1f[2][4];
            #pragma unroll
            for (int mi = 0; mi < 2; ++mi) {
                LDSM4(a0f[mi], swadr(A0b, mw + mi * 16 + a_row, kc + a_col));
                LDSM4(a1f[mi], swadr(A1b, mw + mi * 16 + a_row, kc + a_col));
            }
            uint32_t b0f[8][2], b1f[8][2];
            #pragma unroll
            for (int nb = 0; nb < 4; ++nb) {
                uint32_t r4[4];
                LDSM4(r4, swadr(B0b, nw + nb * 16 + b_row, kc + b_col));
                b0f[nb*2][0] = r4[0]; b0f[nb*2][1] = r4[1];
                b0f[nb*2+1][0] = r4[2]; b0f[nb*2+1][1] = r4[3];
                LDSM4(r4, swadr(B1b, nw + nb * 16 + b_row, kc + b_col));
                b1f[nb*2][0] = r4[0]; b1f[nb*2][1] = r4[1];
                b1f[nb*2+1][0] = r4[2]; b1f[nb*2+1][1] = r4[3];
            }
            #pragma unroll
            for (int mi = 0; mi < 2; ++mi)
                #pragma unroll
                for (int nj = 0; nj < 8; ++nj)
                    MMA16816(acc[mi][nj], a0f[mi], b0f[nj]);
            #pragma unroll
            for (int mi = 0; mi < 2; ++mi)
                #pragma unroll
                for (int nj = 0; nj < 8; ++nj)
                    MMA16816(acc[mi][nj], a0f[mi], b1f[nj]);
            #pragma unroll
            for (int mi = 0; mi < 2; ++mi)
                #pragma unroll
                for (int nj = 0; nj < 8; ++nj)
                    MMA16816(acc[mi][nj], a1f[mi], b0f[nj]);
        }
        __syncthreads();
    }

    // epilogue: write partials
    float* zp = g_zpart + ((size_t)kz * BATCH + m0) * NOUT;
    #pragma unroll
    for (int mi = 0; mi < 2; ++mi)
        #pragma unroll
        for (int nj = 0; nj < 8; ++nj) {
            int m = mw + mi * 16 + lr;
            int n = nw + nj * 8 + lc * 2;
            *(float2*)&zp[(size_t)m * NOUT + n] =
                make_float2(acc[mi][nj][0], acc[mi][nj][1]);
            *(float2*)&zp[(size_t)(m + 8) * NOUT + n] =
                make_float2(acc[mi][nj][2], acc[mi][nj][3]);
        }
}

// ---------------------------------------------------------------------------
// Kernel 3: reduce split-K partials + bias; mean | softplus(std)
// ---------------------------------------------------------------------------
__global__ __launch_bounds__(256) void epi_kernel(const float* __restrict__ bout,
                                                  float* __restrict__ out)
{
    int idx = blockIdx.x * 256 + threadIdx.x;
    if (idx >= BATCH * NOUT) return;
    int b = idx / NOUT, n = idx % NOUT;
    float s = bout[n];
    #pragma unroll
    for (int z = 0; z < KSPLIT; ++z)
        s += g_zpart[((size_t)z * BATCH + b) * NOUT + n];
    if (n < Z0) {
        out[(size_t)b * Z0 + n] = s;
    } else {
        float v = fmaxf(s, 0.f) + log1pf(expf(-fabsf(s)));   // stable softplus
        out[(size_t)BATCH * Z0 + (size_t)b * Z0 + (n - Z0)] = v;
    }
}

// ---------------------------------------------------------------------------
extern "C" void kernel_launch(void* const* d_in, const int* in_sizes, int n_in,
                              void* d_out, int out_size)
{
    const float* x    = (const float*)d_in[0];
    // d_in[1] = observed_tp (unused by the reference computation)
    const float* w1   = (const float*)d_in[2];
    const float* b1   = (const float*)d_in[3];
    const float* w2   = (const float*)d_in[4];
    const float* b2   = (const float*)d_in[5];
    const float* w3   = (const float*)d_in[6];
    const float* b3   = (const float*)d_in[7];
    const float* wout = (const float*)d_in[8];
    const float* bout = (const float*)d_in[9];
    float* out = (float*)d_out;

    cudaFuncSetAttribute(mma_gemm,
                         cudaFuncAttributeMaxDynamicSharedMemorySize, GEMM_SMEM);

    wconv_kernel<<<(NOUT * SIGCH + 255) / 256, 256>>>(wout);
    sig_kernel<<<BATCH, 224>>>(x, w1, b1, w2, b2, w3, b3);
    mma_gemm<<<dim3(BATCH / 128, KSPLIT), 256, GEMM_SMEM>>>();
    epi_kernel<<<(BATCH * NOUT + 255) / 256, 256>>>(bout, out);
}